// round 13
// baseline (speedup 1.0000x reference)
#include <cuda_runtime.h>

// ---------------- problem constants ----------------
#define NTOT 2048      // N*T
#define JROWS 288      // 36 tiles * 8 n-chunks
#define EPSV 1e-6f

typedef unsigned long long u64;

// ---------------- scratch (device globals; no allocation) ----------------
static __device__ __align__(16) float g_part1[1048576];
static __device__ __align__(16) float g_WF  [4 * 128 * 128];
static __device__ __align__(16) float g_bb  [256];
static __device__ __align__(16) float g_Gpart[8 * 128 * 128];
static __device__ __align__(16) float g_Hraw[NTOT * 128];
static __device__ __align__(16) float g_H   [NTOT * 128];
static __device__ __align__(16) float g_logH[NTOT * 128];
static __device__ __align__(16) float g_jpart[JROWS * 128];
static __device__ __align__(16) float g_Y   [2 * NTOT * 128];
static __device__ __align__(16) float g_partZ[2 * 32 * 128 * 128];
static __device__ __align__(16) float g_Zw  [2 * 128 * 128];

// ---------------- f32x2 helpers ----------------
__device__ __forceinline__ u64 pack_dup(float x) {
    u64 r; asm("mov.b64 %0, {%1, %1};" : "=l"(r) : "f"(x)); return r;
}
__device__ __forceinline__ void ffma2(u64& d, u64 a, u64 b) {
    asm("fma.rn.f32x2 %0, %1, %2, %0;" : "+l"(d) : "l"(a), "l"(b));
}
__device__ __forceinline__ float4 accrow(u64 a, u64 b) {
    float4 r;
    asm("mov.b64 {%0, %1}, %4;\n\tmov.b64 {%2, %3}, %5;"
        : "=f"(r.x), "=f"(r.y), "=f"(r.z), "=f"(r.w) : "l"(a), "l"(b));
    return r;
}

// ---------------- tile loaders (256 threads, BK=16, BN=128) ----------------
__device__ __forceinline__ void ldgB(const float* __restrict__ B, int ldb, int kRow,
                                     int tid, float4& r0, float4& r1) {
    int i0 = tid * 2, i1 = i0 + 1;
    r0 = *(const float4*)(B + (size_t)(kRow + (i0 >> 5)) * ldb + (i0 & 31) * 4);
    r1 = *(const float4*)(B + (size_t)(kRow + (i1 >> 5)) * ldb + (i1 & 31) * 4);
}
__device__ __forceinline__ void stsB(float* sB, int tid, float4 r0, float4 r1) {
    int i0 = tid * 2, i1 = i0 + 1;
    *(float4*)(sB + (i0 >> 5) * 128 + (i0 & 31) * 4) = r0;
    *(float4*)(sB + (i1 >> 5) * 128 + (i1 & 31) * 4) = r1;
}
// A tile for TN (A K-major [K x 128]); direct copy into sA [16][68]
__device__ __forceinline__ float4 ldgAt(const float* __restrict__ A, int mBase,
                                        int k0, int tid) {
    return *(const float4*)(A + (size_t)(k0 + (tid >> 4)) * 128 + mBase + (tid & 15) * 4);
}
__device__ __forceinline__ void stsAt(float* sA, int tid, float4 v) {
    *(float4*)(sA + (tid >> 4) * 68 + (tid & 15) * 4) = v;
}
// A tile NN BM=64: sA transposed [16][68]
__device__ __forceinline__ float4 ldgA64(const float* __restrict__ A, int lda,
                                         int rowBase, int k0, int tid) {
    return *(const float4*)(A + (size_t)(rowBase + (tid >> 2)) * lda + k0 + (tid & 3) * 4);
}
__device__ __forceinline__ void stsA64(float* sA, int tid, float4 v) {
    int r = tid >> 2, kc = (tid & 3) * 4;
    sA[(kc + 0) * 68 + r] = v.x;
    sA[(kc + 1) * 68 + r] = v.y;
    sA[(kc + 2) * 68 + r] = v.z;
    sA[(kc + 3) * 68 + r] = v.w;
}
// A tile NN BM=32: sA transposed [16][36]; only tids < 128 participate
__device__ __forceinline__ float4 ldgA32(const float* __restrict__ A, int lda,
                                         int rowBase, int k0, int tid) {
    return *(const float4*)(A + (size_t)(rowBase + (tid >> 2)) * lda + k0 + (tid & 3) * 4);
}
__device__ __forceinline__ void stsA32(float* sA, int tid, float4 v) {
    int r = tid >> 2, kc = (tid & 3) * 4;
    sA[(kc + 0) * 36 + r] = v.x;
    sA[(kc + 1) * 36 + r] = v.y;
    sA[(kc + 2) * 36 + r] = v.z;
    sA[(kc + 3) * 36 + r] = v.w;
}

// ---------------- compute blocks ----------------
__device__ __forceinline__ void comp64(const float* sA, const float* sB,
                                       u64 (&acc)[4][4], int tx, int ty) {
#pragma unroll
    for (int k = 0; k < 16; k++) {
        float4 a4 = *(const float4*)(sA + k * 68 + ty * 4);
        ulonglong2 b0 = *(const ulonglong2*)(sB + k * 128 + tx * 4);
        ulonglong2 b1 = *(const ulonglong2*)(sB + k * 128 + 64 + tx * 4);
        u64 d0 = pack_dup(a4.x), d1 = pack_dup(a4.y), d2 = pack_dup(a4.z), d3 = pack_dup(a4.w);
        ffma2(acc[0][0], d0, b0.x); ffma2(acc[0][1], d0, b0.y);
        ffma2(acc[0][2], d0, b1.x); ffma2(acc[0][3], d0, b1.y);
        ffma2(acc[1][0], d1, b0.x); ffma2(acc[1][1], d1, b0.y);
        ffma2(acc[1][2], d1, b1.x); ffma2(acc[1][3], d1, b1.y);
        ffma2(acc[2][0], d2, b0.x); ffma2(acc[2][1], d2, b0.y);
        ffma2(acc[2][2], d2, b1.x); ffma2(acc[2][3], d2, b1.y);
        ffma2(acc[3][0], d3, b0.x); ffma2(acc[3][1], d3, b0.y);
        ffma2(acc[3][2], d3, b1.x); ffma2(acc[3][3], d3, b1.y);
    }
}
__device__ __forceinline__ void comp32(const float* sA, const float* sB,
                                       u64 (&acc)[2][4], int tx, int ty) {
#pragma unroll
    for (int k = 0; k < 16; k++) {
        float2 a2 = *(const float2*)(sA + k * 36 + ty * 2);
        ulonglong2 b0 = *(const ulonglong2*)(sB + k * 128 + tx * 4);
        ulonglong2 b1 = *(const ulonglong2*)(sB + k * 128 + 64 + tx * 4);
        u64 d0 = pack_dup(a2.x), d1 = pack_dup(a2.y);
        ffma2(acc[0][0], d0, b0.x); ffma2(acc[0][1], d0, b0.y);
        ffma2(acc[0][2], d0, b1.x); ffma2(acc[0][3], d0, b1.y);
        ffma2(acc[1][0], d1, b0.x); ffma2(acc[1][1], d1, b0.y);
        ffma2(acc[1][2], d1, b1.x); ffma2(acc[1][3], d1, b1.y);
    }
}

// ---------------- block reductions ----------------
template <int NW>
__device__ __forceinline__ float block_sum(float v) {
    __shared__ float sred[8];
    __syncthreads();
#pragma unroll
    for (int o = 16; o; o >>= 1) v += __shfl_xor_sync(0xffffffffu, v, o);
    if ((threadIdx.x & 31) == 0) sred[threadIdx.x >> 5] = v;
    __syncthreads();
    float t = 0.f;
#pragma unroll
    for (int k = 0; k < NW; k++) t += sred[k];
    return t;
}
template <int NW>
__device__ __forceinline__ float block_max(float v) {
    __shared__ float sred[8];
    __syncthreads();
#pragma unroll
    for (int o = 16; o; o >>= 1) v = fmaxf(v, __shfl_xor_sync(0xffffffffu, v, o));
    if ((threadIdx.x & 31) == 0) sred[threadIdx.x >> 5] = v;
    __syncthreads();
    float t = -3.4e38f;
#pragma unroll
    for (int k = 0; k < NW; k++) t = fmaxf(t, sred[k]);
    return t;
}

// ================= stageA: part1(128) + Y(64) + WF(16) + bb(1) in ONE launch =================
__global__ __launch_bounds__(256) void k_stageA(
    const float* __restrict__ xt, const float* __restrict__ xn,
    const float* __restrict__ w_it, const float* __restrict__ w_inw,
    const float* __restrict__ w_t2n, const float* __restrict__ w_n2t,
    const float* __restrict__ th_t, const float* __restrict__ th_n,
    const float* __restrict__ w2_it, const float* __restrict__ w2_inw,
    const float* __restrict__ w2_t2n, const float* __restrict__ w2_n2t,
    const float* __restrict__ fW1,
    const float* __restrict__ b2_it, const float* __restrict__ b2_inw,
    const float* __restrict__ b2_t2n, const float* __restrict__ b2_n2t)
{
    __shared__ __align__(16) float sA[16 * 68];
    __shared__ __align__(16) float sB[16 * 128];
    int tid = threadIdx.x, tx = tid & 15, ty = tid >> 4;
    int bx = blockIdx.x;

    if (bx < 128) {
        int head = bx >> 5, r = bx & 31;
        int mBase = (r & 1) * 64;
        int kBeg = (r >> 1) * 128;
        const float* A = (head == 0 || head == 3) ? xt : xn;
        const float* B = (head == 0) ? w_it : (head == 1) ? w_inw : (head == 2) ? w_t2n : w_n2t;
        u64 acc[4][4] = {};
        float4 ra = ldgAt(A, mBase, kBeg, tid);
        float4 rb0, rb1; ldgB(B, 128, kBeg, tid, rb0, rb1);
        for (int s = 0; s < 8; s++) {
            __syncthreads();
            stsAt(sA, tid, ra); stsB(sB, tid, rb0, rb1);
            __syncthreads();
            if (s < 7) { ra = ldgAt(A, mBase, kBeg + (s + 1) * 16, tid); ldgB(B, 128, kBeg + (s + 1) * 16, tid, rb0, rb1); }
            comp64(sA, sB, acc, tx, ty);
        }
        float* C = g_part1 + (size_t)(head * 16 + (r >> 1)) * 16384;
        int r0 = mBase + ty * 4;
#pragma unroll
        for (int u = 0; u < 4; u++) {
            *(float4*)(C + (r0 + u) * 128 + tx * 4)      = accrow(acc[u][0], acc[u][1]);
            *(float4*)(C + (r0 + u) * 128 + 64 + tx * 4) = accrow(acc[u][2], acc[u][3]);
        }
    } else if (bx < 192) {
        int idx = bx - 128;
        int side = idx >> 5;
        int rowBase = (idx & 31) * 64;
        const float* A = side ? xn : xt;
        const float* B = side ? th_n : th_t;
        u64 acc[4][4] = {};
        float4 ra = ldgA64(A, 128, rowBase, 0, tid);
        float4 rb0, rb1; ldgB(B, 128, 0, tid, rb0, rb1);
        for (int s = 0; s < 8; s++) {
            __syncthreads();
            stsA64(sA, tid, ra); stsB(sB, tid, rb0, rb1);
            __syncthreads();
            if (s < 7) { ra = ldgA64(A, 128, rowBase, (s + 1) * 16, tid); ldgB(B, 128, (s + 1) * 16, tid, rb0, rb1); }
            comp64(sA, sB, acc, tx, ty);
        }
        float* C = g_Y + (size_t)side * NTOT * 128;
        int r0 = rowBase + ty * 4;
#pragma unroll
        for (int u = 0; u < 4; u++) {
            *(float4*)(C + (size_t)(r0 + u) * 128 + tx * 4)      = accrow(acc[u][0], acc[u][1]);
            *(float4*)(C + (size_t)(r0 + u) * 128 + 64 + tx * 4) = accrow(acc[u][2], acc[u][3]);
        }
    } else if (bx < 208) {
        int idx = bx - 192;
        int head = idx >> 2;
        int rowBase = (idx & 3) * 32;
        const float* A = (head == 0) ? w2_it : (head == 1) ? w2_inw : (head == 2) ? w2_t2n : w2_n2t;
        const float* B = fW1 + head * 128 * 128;
        u64 acc[2][4] = {};
        float4 ra; if (tid < 128) ra = ldgA32(A, 128, rowBase, 0, tid);
        float4 rb0, rb1; ldgB(B, 128, 0, tid, rb0, rb1);
        for (int s = 0; s < 8; s++) {
            __syncthreads();
            if (tid < 128) stsA32(sA, tid, ra);
            stsB(sB, tid, rb0, rb1);
            __syncthreads();
            if (s < 7) { if (tid < 128) ra = ldgA32(A, 128, rowBase, (s + 1) * 16, tid); ldgB(B, 128, (s + 1) * 16, tid, rb0, rb1); }
            comp32(sA, sB, acc, tx, ty);
        }
        float* C = g_WF + head * 16384;
        int r0 = rowBase + ty * 2;
#pragma unroll
        for (int u = 0; u < 2; u++) {
            *(float4*)(C + (r0 + u) * 128 + tx * 4)      = accrow(acc[u][0], acc[u][1]);
            *(float4*)(C + (r0 + u) * 128 + 64 + tx * 4) = accrow(acc[u][2], acc[u][3]);
        }
    } else {
        int side = tid >> 7, e = tid & 127;
        float s = 0.f;
#pragma unroll
        for (int p = 0; p < 2; p++) {
            int h = side + p * 2;
            const float* b2 = (h == 0) ? b2_it : (h == 1) ? b2_inw : (h == 2) ? b2_t2n : b2_n2t;
            const float* F = fW1 + h * 128 * 128;
            for (int k = 0; k < 128; k++) s += b2[k] * F[k * 128 + e];
        }
        g_bb[side * 128 + e] = s;
    }
}

// ================= k_G: split-K partials of G = sum_h relu(b1+sum16 part1)_h @ WF_h =========
// grid (2 m-tiles, 4 chunks, 2 sides); chunk c: head = side + (c>>1)*2, kOff = (c&1)*64
// A-loader fuses red1: relu(b1 + sum of 16 part1 chunks).
__global__ __launch_bounds__(256) void k_G(
    const float* __restrict__ b1_it, const float* __restrict__ b1_inw,
    const float* __restrict__ b1_t2n, const float* __restrict__ b1_n2t)
{
    __shared__ __align__(16) float sA[16 * 68];
    __shared__ __align__(16) float sB[16 * 128];
    int side = blockIdx.z, chunk = blockIdx.y;
    int head = side + (chunk >> 1) * 2;
    int kOff = (chunk & 1) * 64;
    int mBase = blockIdx.x * 64;
    const float* parts = g_part1 + (size_t)head * 16 * 16384;
    const float* b1 = (head == 0) ? b1_it : (head == 1) ? b1_inw : (head == 2) ? b1_t2n : b1_n2t;
    const float* B = g_WF + head * 16384;
    int tid = threadIdx.x, tx = tid & 15, ty = tid >> 4;

    auto ldA = [&](int k0) -> float4 {
        int row = mBase + (tid >> 2);
        int kc = k0 + (tid & 3) * 4;
        float4 s = *(const float4*)(b1 + kc);
#pragma unroll
        for (int c = 0; c < 16; c++) {
            float4 p = *(const float4*)(parts + (size_t)c * 16384 + row * 128 + kc);
            s.x += p.x; s.y += p.y; s.z += p.z; s.w += p.w;
        }
        s.x = fmaxf(s.x, 0.f); s.y = fmaxf(s.y, 0.f); s.z = fmaxf(s.z, 0.f); s.w = fmaxf(s.w, 0.f);
        return s;
    };

    u64 acc[4][4] = {};
    float4 ra = ldA(kOff);
    float4 rb0, rb1; ldgB(B, 128, kOff, tid, rb0, rb1);
    for (int s = 0; s < 4; s++) {
        __syncthreads();
        stsA64(sA, tid, ra); stsB(sB, tid, rb0, rb1);
        __syncthreads();
        if (s < 3) { ra = ldA(kOff + (s + 1) * 16); ldgB(B, 128, kOff + (s + 1) * 16, tid, rb0, rb1); }
        comp64(sA, sB, acc, tx, ty);
    }
    float* C = g_Gpart + (size_t)(side * 4 + chunk) * 16384;
    int r0 = mBase + ty * 4;
#pragma unroll
    for (int u = 0; u < 4; u++) {
        *(float4*)(C + (r0 + u) * 128 + tx * 4)      = accrow(acc[u][0], acc[u][1]);
        *(float4*)(C + (r0 + u) * 128 + 64 + tx * 4) = accrow(acc[u][2], acc[u][3]);
    }
}

// ================= k_HtmpF2: Hraw = relu(xt@G0 + xn@G1 + fb1) @ fW2 + fb2 ==========
// B-loader for phase 1 sums the 4 G-partials + bb inline (fused redG).
// Phase 2 keeps the relu tile in smem (A layout) and multiplies by fW2 (fused f2).
__global__ __launch_bounds__(256) void k_HtmpF2(
    const float* __restrict__ xt, const float* __restrict__ xn,
    const float* __restrict__ fb1, const float* __restrict__ fW2,
    const float* __restrict__ fb2)
{
    __shared__ __align__(16) float sA[16 * 36];
    __shared__ __align__(16) float sB[16 * 128];
    __shared__ __align__(16) float sT[128 * 36];
    int rowBase = blockIdx.x * 32;
    int tid = threadIdx.x, tx = tid & 15, ty = tid >> 4;

    u64 acc[2][4] = {};
#pragma unroll
    for (int pass = 0; pass < 2; pass++) {
        const float* A = pass ? xn : xt;
        const float* gp = g_Gpart + (size_t)pass * 4 * 16384;
        const float4* bbv = (const float4*)(g_bb + pass * 128);

        auto ldB_G = [&](int kRow, float4& r0, float4& r1) {
            int i0 = tid * 2, i1 = i0 + 1;
            int row0 = kRow + (i0 >> 5), col0 = (i0 & 31);
            int row1 = kRow + (i1 >> 5), col1 = (i1 & 31);
            float4 s0 = bbv[col0], s1 = bbv[col1];
#pragma unroll
            for (int c = 0; c < 4; c++) {
                float4 p0 = *(const float4*)(gp + (size_t)c * 16384 + row0 * 128 + col0 * 4);
                float4 p1 = *(const float4*)(gp + (size_t)c * 16384 + row1 * 128 + col1 * 4);
                s0.x += p0.x; s0.y += p0.y; s0.z += p0.z; s0.w += p0.w;
                s1.x += p1.x; s1.y += p1.y; s1.z += p1.z; s1.w += p1.w;
            }
            r0 = s0; r1 = s1;
        };

        float4 ra; if (tid < 128) ra = ldgA32(A, 128, rowBase, 0, tid);
        float4 rb0, rb1; ldB_G(0, rb0, rb1);
        for (int s = 0; s < 8; s++) {
            __syncthreads();
            if (tid < 128) stsA32(sA, tid, ra);
            stsB(sB, tid, rb0, rb1);
            __syncthreads();
            if (s < 7) { if (tid < 128) ra = ldgA32(A, 128, rowBase, (s + 1) * 16, tid); ldB_G((s + 1) * 16, rb0, rb1); }
            comp32(sA, sB, acc, tx, ty);
        }
        __syncthreads();
    }

    // relu(acc + fb1) -> sT in transposed A layout: sT[c*36 + m], m = local row
    float4 bb0 = *(const float4*)(fb1 + tx * 4);
    float4 bb1 = *(const float4*)(fb1 + 64 + tx * 4);
#pragma unroll
    for (int u = 0; u < 2; u++) {
        int m = ty * 2 + u;
        float4 v0 = accrow(acc[u][0], acc[u][1]);
        float4 v1 = accrow(acc[u][2], acc[u][3]);
        v0.x = fmaxf(v0.x + bb0.x, 0.f); v0.y = fmaxf(v0.y + bb0.y, 0.f);
        v0.z = fmaxf(v0.z + bb0.z, 0.f); v0.w = fmaxf(v0.w + bb0.w, 0.f);
        v1.x = fmaxf(v1.x + bb1.x, 0.f); v1.y = fmaxf(v1.y + bb1.y, 0.f);
        v1.z = fmaxf(v1.z + bb1.z, 0.f); v1.w = fmaxf(v1.w + bb1.w, 0.f);
        int c0 = tx * 4;
        sT[(c0 + 0) * 36 + m] = v0.x; sT[(c0 + 1) * 36 + m] = v0.y;
        sT[(c0 + 2) * 36 + m] = v0.z; sT[(c0 + 3) * 36 + m] = v0.w;
        int c1 = 64 + tx * 4;
        sT[(c1 + 0) * 36 + m] = v1.x; sT[(c1 + 1) * 36 + m] = v1.y;
        sT[(c1 + 2) * 36 + m] = v1.z; sT[(c1 + 3) * 36 + m] = v1.w;
    }

    // phase 2: Hraw = T @ fW2 + fb2
    u64 acc2[2][4] = {};
    float4 rb0, rb1; ldgB(fW2, 128, 0, tid, rb0, rb1);
    for (int s = 0; s < 8; s++) {
        __syncthreads();
        stsB(sB, tid, rb0, rb1);
        __syncthreads();
        if (s < 7) ldgB(fW2, 128, (s + 1) * 16, tid, rb0, rb1);
        comp32(sT + s * 16 * 36, sB, acc2, tx, ty);
    }
    float4 cb0 = *(const float4*)(fb2 + tx * 4);
    float4 cb1 = *(const float4*)(fb2 + 64 + tx * 4);
    int r0 = rowBase + ty * 2;
#pragma unroll
    for (int u = 0; u < 2; u++) {
        float4 v0 = accrow(acc2[u][0], acc2[u][1]);
        float4 v1 = accrow(acc2[u][2], acc2[u][3]);
        v0.x += cb0.x; v0.y += cb0.y; v0.z += cb0.z; v0.w += cb0.w;
        v1.x += cb1.x; v1.y += cb1.y; v1.z += cb1.z; v1.w += cb1.w;
        *(float4*)(g_Hraw + (size_t)(r0 + u) * 128 + tx * 4) = v0;
        *(float4*)(g_Hraw + (size_t)(r0 + u) * 128 + 64 + tx * 4) = v1;
    }
}

// ================= k_colsm: per-column standardize + softmax -> H, logH =================
__global__ __launch_bounds__(256) void k_colsm()
{
    int e = blockIdx.x;
    __shared__ float s[NTOT];
    int tid = threadIdx.x;
    for (int n = tid; n < NTOT; n += 256) s[n] = g_Hraw[n * 128 + e];
    __syncthreads();

    float lsum = 0.f;
    for (int n = tid; n < NTOT; n += 256) lsum += s[n];
    float mean = block_sum<8>(lsum) * (1.f / NTOT);

    float lss = 0.f;
    for (int n = tid; n < NTOT; n += 256) { float d = s[n] - mean; lss += d * d; }
    float var = block_sum<8>(lss) * (1.f / (NTOT - 1));
    float inv = 1.f / (sqrtf(var) + EPSV);

    float lmax = -3.4e38f;
    for (int n = tid; n < NTOT; n += 256) {
        float z = (s[n] - mean) * inv;
        s[n] = z;
        lmax = fmaxf(lmax, z);
    }
    __syncthreads();
    float mx = block_max<8>(lmax);

    float lse = 0.f;
    for (int n = tid; n < NTOT; n += 256) lse += __expf(s[n] - mx);
    float sum = block_sum<8>(lse);
    float invs = 1.f / sum;
    float lls = __logf(sum);

    for (int n = tid; n < NTOT; n += 256) {
        float z = s[n];
        g_H[n * 128 + e]    = __expf(z - mx) * invs;
        g_logH[n * 128 + e] = (z - mx) - lls;
    }
}

// ================= stageB: partZ(128 CTAs) + jsd(288 CTAs) in ONE launch =================
__global__ __launch_bounds__(256) void k_stageB()
{
    __shared__ __align__(16) float smem[3136];
    int tid = threadIdx.x;
    int bx = blockIdx.x;

    if (bx < 128) {
        int side = bx >> 6;
        int r = bx & 63;
        int mBase = (r & 1) * 64;
        int kBeg = (r >> 1) * 64;
        float* sA = smem;
        float* sB = smem + 1088;
        const float* B = g_Y + (size_t)side * NTOT * 128;
        int tx = tid & 15, ty = tid >> 4;
        u64 acc[4][4] = {};
        float4 ra = ldgAt(g_H, mBase, kBeg, tid);
        float4 rb0, rb1; ldgB(B, 128, kBeg, tid, rb0, rb1);
        for (int s = 0; s < 4; s++) {
            __syncthreads();
            stsAt(sA, tid, ra); stsB(sB, tid, rb0, rb1);
            __syncthreads();
            if (s < 3) { ra = ldgAt(g_H, mBase, kBeg + (s + 1) * 16, tid); ldgB(B, 128, kBeg + (s + 1) * 16, tid, rb0, rb1); }
            comp64(sA, sB, acc, tx, ty);
        }
        float* C = g_partZ + (size_t)(side * 32 + (r >> 1)) * 16384;
        int r0 = mBase + ty * 4;
#pragma unroll
        for (int u = 0; u < 4; u++) {
            *(float4*)(C + (r0 + u) * 128 + tx * 4)      = accrow(acc[u][0], acc[u][1]);
            *(float4*)(C + (r0 + u) * 128 + 64 + tx * 4) = accrow(acc[u][2], acc[u][3]);
        }
    } else {
        int idx = bx - 128;
        int t = idx % 36;
        int nch = idx / 36;
        int bi = 0, rem = t;
        while (rem >= 8 - bi) { rem -= 8 - bi; bi++; }
        int bj = bi + rem;
        int ti = tid & 15, tj = tid >> 4;
        int i = bi * 16 + ti, j = bj * 16 + tj;

        float* sHi = smem;
        float* sLi = smem + 256;
        float* sHj = smem + 512;
        float* sLj = smem + 768;
        float* red = smem + 1024;

        float acci = 0.f, accj = 0.f;
        int lr = tid >> 4, lc = tid & 15;
        int nBeg = nch * 256;

        for (int n0 = nBeg; n0 < nBeg + 256; n0 += 16) {
            __syncthreads();
            int n = n0 + lr;
            sHi[lr * 16 + lc] = g_H   [n * 128 + bi * 16 + lc];
            sLi[lr * 16 + lc] = g_logH[n * 128 + bi * 16 + lc];
            sHj[lr * 16 + lc] = g_H   [n * 128 + bj * 16 + lc];
            sLj[lr * 16 + lc] = g_logH[n * 128 + bj * 16 + lc];
            __syncthreads();
#pragma unroll
            for (int r2 = 0; r2 < 16; r2++) {
                float hi = sHi[r2 * 16 + ti], hj = sHj[r2 * 16 + tj];
                float m  = 0.5f * (hi + hj);
                float lm = __logf(m);
                acci += hi * (sLi[r2 * 16 + ti] - lm);
                accj += hj * (sLj[r2 * 16 + tj] - lm);
            }
        }
        float v = (i < j) ? 0.5f * (acci + accj) : 0.f;

        __syncthreads();
        red[tj * 16 + ti] = v;
        __syncthreads();

        float* out = g_jpart + (size_t)(nch * 36 + t) * 128;
        if (tid < 128) out[tid] = 0.f;
        __syncthreads();
        if (tid < 16) {
            float si = 0.f, sj = 0.f;
#pragma unroll
            for (int r2 = 0; r2 < 16; r2++) { si += red[r2 * 16 + tid]; sj += red[tid * 16 + r2]; }
            out[bi * 16 + tid] += si;
            out[bj * 16 + tid] += sj;
        }
    }
}

// ================= k_redZw: (recompute w per CTA) + Zw = w * sum(partZ chunks) ==========
__global__ __launch_bounds__(256) void k_redZw()
{
    __shared__ float ws[128];
    int tid = threadIdx.x;
    int side = blockIdx.y;

    // each thread computes jm for e = tid & 127 (duplicated x2 across the block)
    int e = tid & 127;
    float cs = 0.f;
    for (int r = 0; r < JROWS; r++) cs += g_jpart[r * 128 + e];
    float jm = cs * (1.f / 128.f);

    float mean = block_sum<8>(jm) * (0.5f / 128.f);
    float d = jm - mean;
    float var = block_sum<8>(d * d) * (0.5f / 127.f);
    float njm = d / (sqrtf(var) + EPSV);
    float mx = block_max<8>(njm);
    float ex = __expf(njm - mx);
    float sum = block_sum<8>(ex) * 0.5f;
    if (tid < 128) ws[tid] = ex / sum;
    __syncthreads();

    int i4 = blockIdx.x * 256 + tid;          // < 4096
    float4 s = make_float4(0.f, 0.f, 0.f, 0.f);
#pragma unroll
    for (int c = 0; c < 32; c++) {
        float4 p = ((const float4*)g_partZ)[(size_t)(side * 32 + c) * 4096 + i4];
        s.x += p.x; s.y += p.y; s.z += p.z; s.w += p.w;
    }
    float wv = ws[i4 >> 5];
    s.x *= wv; s.y *= wv; s.z *= wv; s.w *= wv;
    ((float4*)g_Zw)[side * 4096 + i4] = s;
}

// ================= k_final: out = x + elu(H @ Zw) (BM=32) =================
__global__ __launch_bounds__(256) void k_final(
    const float* __restrict__ xt, const float* __restrict__ xn,
    float* __restrict__ out)
{
    __shared__ __align__(16) float sA[16 * 36];
    __shared__ __align__(16) float sB[16 * 128];
    int side = blockIdx.z;
    const float* x = side ? xn : xt;
    const float* B = g_Zw + side * 16384;
    int rowBase = blockIdx.x * 32;
    int tid = threadIdx.x, tx = tid & 15, ty = tid >> 4;
    u64 acc[2][4] = {};
    float4 ra; if (tid < 128) ra = ldgA32(g_H, 128, rowBase, 0, tid);
    float4 rb0, rb1; ldgB(B, 128, 0, tid, rb0, rb1);
    for (int s = 0; s < 8; s++) {
        __syncthreads();
        if (tid < 128) stsA32(sA, tid, ra);
        stsB(sB, tid, rb0, rb1);
        __syncthreads();
        if (s < 7) { if (tid < 128) ra = ldgA32(g_H, 128, rowBase, (s + 1) * 16, tid); ldgB(B, 128, (s + 1) * 16, tid, rb0, rb1); }
        comp32(sA, sB, acc, tx, ty);
    }
    float* o = out + (size_t)side * NTOT * 128;
    int r0 = rowBase + ty * 2;
#pragma unroll
    for (int u = 0; u < 2; u++) {
#pragma unroll
        for (int h = 0; h < 2; h++) {
            float4 v = accrow(acc[u][h * 2], acc[u][h * 2 + 1]);
            int c = h * 64 + tx * 4;
            float4 xv = *(const float4*)(x + (size_t)(r0 + u) * 128 + c);
            v.x = xv.x + ((v.x > 0.f) ? v.x : expm1f(v.x));
            v.y = xv.y + ((v.y > 0.f) ? v.y : expm1f(v.y));
            v.z = xv.z + ((v.z > 0.f) ? v.z : expm1f(v.z));
            v.w = xv.w + ((v.w > 0.f) ? v.w : expm1f(v.w));
            *(float4*)(o + (size_t)(r0 + u) * 128 + c) = v;
        }
    }
}

// ---------------- launch ----------------
extern "C" void kernel_launch(void* const* d_in, const int* in_sizes, int n_in,
                              void* d_out, int out_size)
{
    const float* xt    = (const float*)d_in[0];
    const float* xn    = (const float*)d_in[1];
    const float* itW1  = (const float*)d_in[2];
    const float* itb1  = (const float*)d_in[3];
    const float* itW2  = (const float*)d_in[4];
    const float* itb2  = (const float*)d_in[5];
    const float* inwW1 = (const float*)d_in[6];
    const float* inwb1 = (const float*)d_in[7];
    const float* inwW2 = (const float*)d_in[8];
    const float* inwb2 = (const float*)d_in[9];
    const float* t2nW1 = (const float*)d_in[10];
    const float* t2nb1 = (const float*)d_in[11];
    const float* t2nW2 = (const float*)d_in[12];
    const float* t2nb2 = (const float*)d_in[13];
    const float* n2tW1 = (const float*)d_in[14];
    const float* n2tb1 = (const float*)d_in[15];
    const float* n2tW2 = (const float*)d_in[16];
    const float* n2tb2 = (const float*)d_in[17];
    const float* fW1   = (const float*)d_in[18];
    const float* fb1   = (const float*)d_in[19];
    const float* fW2   = (const float*)d_in[20];
    const float* fb2   = (const float*)d_in[21];
    const float* thT   = (const float*)d_in[22];
    const float* thN   = (const float*)d_in[23];
    float* out = (float*)d_out;

    k_stageA<<<209, 256>>>(xt, xn, itW1, inwW1, t2nW1, n2tW1, thT, thN,
                           itW2, inwW2, t2nW2, n2tW2, fW1,
                           itb2, inwb2, t2nb2, n2tb2);
    k_G     <<<dim3(2, 4, 2), 256>>>(itb1, inwb1, t2nb1, n2tb1);
    k_HtmpF2<<<64, 256>>>(xt, xn, fb1, fW2, fb2);
    k_colsm <<<128, 256>>>();
    k_stageB<<<416, 256>>>();
    k_redZw <<<dim3(16, 2), 256>>>();
    k_final <<<dim3(64, 1, 2), 256>>>(xt, xn, out);
}

// round 14
// speedup vs baseline: 1.0820x; 1.0820x over previous
#include <cuda_runtime.h>

// ---------------- problem constants ----------------
#define NTOT 2048      // N*T
#define JROWS 288      // 36 tiles * 8 n-chunks
#define EPSV 1e-6f

typedef unsigned long long u64;

// ---------------- scratch (device globals; no allocation) ----------------
static __device__ __align__(16) float g_part1[1048576];
static __device__ __align__(16) float g_P1  [4 * 128 * 128];
static __device__ __align__(16) float g_WF  [4 * 128 * 128];
static __device__ __align__(16) float g_bb  [256];
static __device__ __align__(16) float g_G   [2 * 128 * 128];
static __device__ __align__(16) float g_Htmp[NTOT * 128];
static __device__ __align__(16) float g_HrawT[128 * NTOT];   // transposed [e][n]
static __device__ __align__(16) float g_HT  [128 * NTOT];    // transposed [e][n]
static __device__ __align__(16) float g_logHT[128 * NTOT];   // transposed [e][n]
static __device__ __align__(16) float g_jpart[JROWS * 128];
static __device__ __align__(16) float g_w   [128];
static __device__ __align__(16) float g_Y   [2 * NTOT * 128];
static __device__ __align__(16) float g_partZ[2 * 32 * 128 * 128];
static __device__ __align__(16) float g_Zw  [2 * 128 * 128];

// ---------------- f32x2 helpers ----------------
__device__ __forceinline__ u64 pack_dup(float x) {
    u64 r; asm("mov.b64 %0, {%1, %1};" : "=l"(r) : "f"(x)); return r;
}
__device__ __forceinline__ void ffma2(u64& d, u64 a, u64 b) {
    asm("fma.rn.f32x2 %0, %1, %2, %0;" : "+l"(d) : "l"(a), "l"(b));
}
__device__ __forceinline__ float4 accrow(u64 a, u64 b) {
    float4 r;
    asm("mov.b64 {%0, %1}, %4;\n\tmov.b64 {%2, %3}, %5;"
        : "=f"(r.x), "=f"(r.y), "=f"(r.z), "=f"(r.w) : "l"(a), "l"(b));
    return r;
}

// ---------------- tile loaders (256 threads, BK=16, BN=128) ----------------
__device__ __forceinline__ void ldgB(const float* __restrict__ B, int ldb, int kRow,
                                     int tid, float4& r0, float4& r1) {
    int i0 = tid * 2, i1 = i0 + 1;
    r0 = *(const float4*)(B + (size_t)(kRow + (i0 >> 5)) * ldb + (i0 & 31) * 4);
    r1 = *(const float4*)(B + (size_t)(kRow + (i1 >> 5)) * ldb + (i1 & 31) * 4);
}
__device__ __forceinline__ void stsB(float* sB, int tid, float4 r0, float4 r1) {
    int i0 = tid * 2, i1 = i0 + 1;
    *(float4*)(sB + (i0 >> 5) * 128 + (i0 & 31) * 4) = r0;
    *(float4*)(sB + (i1 >> 5) * 128 + (i1 & 31) * 4) = r1;
}
// A tile for TN (A K-major [K x 128]); direct copy into sA [16][68]
__device__ __forceinline__ float4 ldgAt(const float* __restrict__ A, int mBase,
                                        int k0, int tid) {
    return *(const float4*)(A + (size_t)(k0 + (tid >> 4)) * 128 + mBase + (tid & 15) * 4);
}
__device__ __forceinline__ void stsAt(float* sA, int tid, float4 v) {
    *(float4*)(sA + (tid >> 4) * 68 + (tid & 15) * 4) = v;
}
// A tile NN BM=64: sA transposed [16][68]
__device__ __forceinline__ float4 ldgA64(const float* __restrict__ A, int lda,
                                         int rowBase, int k0, int tid) {
    return *(const float4*)(A + (size_t)(rowBase + (tid >> 2)) * lda + k0 + (tid & 3) * 4);
}
__device__ __forceinline__ void stsA64(float* sA, int tid, float4 v) {
    int r = tid >> 2, kc = (tid & 3) * 4;
    sA[(kc + 0) * 68 + r] = v.x;
    sA[(kc + 1) * 68 + r] = v.y;
    sA[(kc + 2) * 68 + r] = v.z;
    sA[(kc + 3) * 68 + r] = v.w;
}
// A tile NN BM=32: sA transposed [16][36]; only tids < 128 participate
__device__ __forceinline__ float4 ldgA32(const float* __restrict__ A, int lda,
                                         int rowBase, int k0, int tid) {
    return *(const float4*)(A + (size_t)(rowBase + (tid >> 2)) * lda + k0 + (tid & 3) * 4);
}
__device__ __forceinline__ void stsA32(float* sA, int tid, float4 v) {
    int r = tid >> 2, kc = (tid & 3) * 4;
    sA[(kc + 0) * 36 + r] = v.x;
    sA[(kc + 1) * 36 + r] = v.y;
    sA[(kc + 2) * 36 + r] = v.z;
    sA[(kc + 3) * 36 + r] = v.w;
}
// A tile BM=32 from K-major HT [128 e][2048 n]: direct copy, 128 threads
__device__ __forceinline__ void ldstA_HT(const float* __restrict__ HT, float* sA,
                                         int rowBase, int k0, int tid) {
    float4 v = *(const float4*)(HT + (size_t)(k0 + (tid >> 3)) * NTOT + rowBase + (tid & 7) * 4);
    *(float4*)(sA + (tid >> 3) * 36 + (tid & 7) * 4) = v;
}

// ---------------- compute blocks ----------------
__device__ __forceinline__ void comp64(const float* sA, const float* sB,
                                       u64 (&acc)[4][4], int tx, int ty) {
#pragma unroll
    for (int k = 0; k < 16; k++) {
        float4 a4 = *(const float4*)(sA + k * 68 + ty * 4);
        ulonglong2 b0 = *(const ulonglong2*)(sB + k * 128 + tx * 4);
        ulonglong2 b1 = *(const ulonglong2*)(sB + k * 128 + 64 + tx * 4);
        u64 d0 = pack_dup(a4.x), d1 = pack_dup(a4.y), d2 = pack_dup(a4.z), d3 = pack_dup(a4.w);
        ffma2(acc[0][0], d0, b0.x); ffma2(acc[0][1], d0, b0.y);
        ffma2(acc[0][2], d0, b1.x); ffma2(acc[0][3], d0, b1.y);
        ffma2(acc[1][0], d1, b0.x); ffma2(acc[1][1], d1, b0.y);
        ffma2(acc[1][2], d1, b1.x); ffma2(acc[1][3], d1, b1.y);
        ffma2(acc[2][0], d2, b0.x); ffma2(acc[2][1], d2, b0.y);
        ffma2(acc[2][2], d2, b1.x); ffma2(acc[2][3], d2, b1.y);
        ffma2(acc[3][0], d3, b0.x); ffma2(acc[3][1], d3, b0.y);
        ffma2(acc[3][2], d3, b1.x); ffma2(acc[3][3], d3, b1.y);
    }
}
__device__ __forceinline__ void comp32(const float* sA, const float* sB,
                                       u64 (&acc)[2][4], int tx, int ty) {
#pragma unroll
    for (int k = 0; k < 16; k++) {
        float2 a2 = *(const float2*)(sA + k * 36 + ty * 2);
        ulonglong2 b0 = *(const ulonglong2*)(sB + k * 128 + tx * 4);
        ulonglong2 b1 = *(const ulonglong2*)(sB + k * 128 + 64 + tx * 4);
        u64 d0 = pack_dup(a2.x), d1 = pack_dup(a2.y);
        ffma2(acc[0][0], d0, b0.x); ffma2(acc[0][1], d0, b0.y);
        ffma2(acc[0][2], d0, b1.x); ffma2(acc[0][3], d0, b1.y);
        ffma2(acc[1][0], d1, b0.x); ffma2(acc[1][1], d1, b0.y);
        ffma2(acc[1][2], d1, b1.x); ffma2(acc[1][3], d1, b1.y);
    }
}

// ---------------- block reductions ----------------
template <int NW>
__device__ __forceinline__ float block_sum(float v) {
    __shared__ float sred[8];
    __syncthreads();
#pragma unroll
    for (int o = 16; o; o >>= 1) v += __shfl_xor_sync(0xffffffffu, v, o);
    if ((threadIdx.x & 31) == 0) sred[threadIdx.x >> 5] = v;
    __syncthreads();
    float t = 0.f;
#pragma unroll
    for (int k = 0; k < NW; k++) t += sred[k];
    return t;
}
template <int NW>
__device__ __forceinline__ float block_max(float v) {
    __shared__ float sred[8];
    __syncthreads();
#pragma unroll
    for (int o = 16; o; o >>= 1) v = fmaxf(v, __shfl_xor_sync(0xffffffffu, v, o));
    if ((threadIdx.x & 31) == 0) sred[threadIdx.x >> 5] = v;
    __syncthreads();
    float t = -3.4e38f;
#pragma unroll
    for (int k = 0; k < NW; k++) t = fmaxf(t, sred[k]);
    return t;
}

// ================= stageA: part1(128) + Y(64) + WF(16) + bb(1) in ONE launch =================
__global__ __launch_bounds__(256) void k_stageA(
    const float* __restrict__ xt, const float* __restrict__ xn,
    const float* __restrict__ w_it, const float* __restrict__ w_inw,
    const float* __restrict__ w_t2n, const float* __restrict__ w_n2t,
    const float* __restrict__ th_t, const float* __restrict__ th_n,
    const float* __restrict__ w2_it, const float* __restrict__ w2_inw,
    const float* __restrict__ w2_t2n, const float* __restrict__ w2_n2t,
    const float* __restrict__ fW1,
    const float* __restrict__ b2_it, const float* __restrict__ b2_inw,
    const float* __restrict__ b2_t2n, const float* __restrict__ b2_n2t)
{
    __shared__ __align__(16) float sA[16 * 68];
    __shared__ __align__(16) float sB[16 * 128];
    int tid = threadIdx.x, tx = tid & 15, ty = tid >> 4;
    int bx = blockIdx.x;

    if (bx < 128) {
        int head = bx >> 5, r = bx & 31;
        int mBase = (r & 1) * 64;
        int kBeg = (r >> 1) * 128;
        const float* A = (head == 0 || head == 3) ? xt : xn;
        const float* B = (head == 0) ? w_it : (head == 1) ? w_inw : (head == 2) ? w_t2n : w_n2t;
        u64 acc[4][4] = {};
        float4 ra = ldgAt(A, mBase, kBeg, tid);
        float4 rb0, rb1; ldgB(B, 128, kBeg, tid, rb0, rb1);
        for (int s = 0; s < 8; s++) {
            __syncthreads();
            stsAt(sA, tid, ra); stsB(sB, tid, rb0, rb1);
            __syncthreads();
            if (s < 7) { ra = ldgAt(A, mBase, kBeg + (s + 1) * 16, tid); ldgB(B, 128, kBeg + (s + 1) * 16, tid, rb0, rb1); }
            comp64(sA, sB, acc, tx, ty);
        }
        float* C = g_part1 + (size_t)(head * 16 + (r >> 1)) * 16384;
        int r0 = mBase + ty * 4;
#pragma unroll
        for (int u = 0; u < 4; u++) {
            *(float4*)(C + (r0 + u) * 128 + tx * 4)      = accrow(acc[u][0], acc[u][1]);
            *(float4*)(C + (r0 + u) * 128 + 64 + tx * 4) = accrow(acc[u][2], acc[u][3]);
        }
    } else if (bx < 192) {
        int idx = bx - 128;
        int side = idx >> 5;
        int rowBase = (idx & 31) * 64;
        const float* A = side ? xn : xt;
        const float* B = side ? th_n : th_t;
        u64 acc[4][4] = {};
        float4 ra = ldgA64(A, 128, rowBase, 0, tid);
        float4 rb0, rb1; ldgB(B, 128, 0, tid, rb0, rb1);
        for (int s = 0; s < 8; s++) {
            __syncthreads();
            stsA64(sA, tid, ra); stsB(sB, tid, rb0, rb1);
            __syncthreads();
            if (s < 7) { ra = ldgA64(A, 128, rowBase, (s + 1) * 16, tid); ldgB(B, 128, (s + 1) * 16, tid, rb0, rb1); }
            comp64(sA, sB, acc, tx, ty);
        }
        float* C = g_Y + (size_t)side * NTOT * 128;
        int r0 = rowBase + ty * 4;
#pragma unroll
        for (int u = 0; u < 4; u++) {
            *(float4*)(C + (size_t)(r0 + u) * 128 + tx * 4)      = accrow(acc[u][0], acc[u][1]);
            *(float4*)(C + (size_t)(r0 + u) * 128 + 64 + tx * 4) = accrow(acc[u][2], acc[u][3]);
        }
    } else if (bx < 208) {
        int idx = bx - 192;
        int head = idx >> 2;
        int rowBase = (idx & 3) * 32;
        const float* A = (head == 0) ? w2_it : (head == 1) ? w2_inw : (head == 2) ? w2_t2n : w2_n2t;
        const float* B = fW1 + head * 128 * 128;
        u64 acc[2][4] = {};
        float4 ra; if (tid < 128) ra = ldgA32(A, 128, rowBase, 0, tid);
        float4 rb0, rb1; ldgB(B, 128, 0, tid, rb0, rb1);
        for (int s = 0; s < 8; s++) {
            __syncthreads();
            if (tid < 128) stsA32(sA, tid, ra);
            stsB(sB, tid, rb0, rb1);
            __syncthreads();
            if (s < 7) { if (tid < 128) ra = ldgA32(A, 128, rowBase, (s + 1) * 16, tid); ldgB(B, 128, (s + 1) * 16, tid, rb0, rb1); }
            comp32(sA, sB, acc, tx, ty);
        }
        float* C = g_WF + head * 16384;
        int r0 = rowBase + ty * 2;
#pragma unroll
        for (int u = 0; u < 2; u++) {
            *(float4*)(C + (r0 + u) * 128 + tx * 4)      = accrow(acc[u][0], acc[u][1]);
            *(float4*)(C + (r0 + u) * 128 + 64 + tx * 4) = accrow(acc[u][2], acc[u][3]);
        }
    } else {
        int side = tid >> 7, e = tid & 127;
        float s = 0.f;
#pragma unroll
        for (int p = 0; p < 2; p++) {
            int h = side + p * 2;
            const float* b2 = (h == 0) ? b2_it : (h == 1) ? b2_inw : (h == 2) ? b2_t2n : b2_n2t;
            const float* F = fW1 + h * 128 * 128;
            for (int k = 0; k < 128; k++) s += b2[k] * F[k * 128 + e];
        }
        g_bb[side * 128 + e] = s;
    }
}

// ================= K2: reduce 16 chunks + bias + relu -> P1 =================
__global__ __launch_bounds__(256) void k_red1(
    const float* __restrict__ b_it, const float* __restrict__ b_inw,
    const float* __restrict__ b_t2n, const float* __restrict__ b_n2t)
{
    int head = blockIdx.y;
    int i4 = blockIdx.x * 256 + threadIdx.x;   // < 4096 float4s per head
    const float* b = (head == 0) ? b_it : (head == 1) ? b_inw : (head == 2) ? b_t2n : b_n2t;
    float4 s = ((const float4*)b)[i4 & 31];
#pragma unroll
    for (int c = 0; c < 16; c++) {
        float4 p = ((const float4*)g_part1)[(size_t)(head * 16 + c) * 4096 + i4];
        s.x += p.x; s.y += p.y; s.z += p.z; s.w += p.w;
    }
    s.x = fmaxf(s.x, 0.f); s.y = fmaxf(s.y, 0.f); s.z = fmaxf(s.z, 0.f); s.w = fmaxf(s.w, 0.f);
    ((float4*)g_P1)[head * 4096 + i4] = s;
}

// ================= K3: split-K partials of G = sum_h P1_h @ WF_h =================
__global__ __launch_bounds__(256) void k_G()
{
    __shared__ __align__(16) float sA[16 * 68];
    __shared__ __align__(16) float sB[16 * 128];
    int side = blockIdx.z, chunk = blockIdx.y;
    int head = side + (chunk >> 1) * 2;
    int kOff = (chunk & 1) * 64;
    int mBase = blockIdx.x * 64;
    const float* A = g_P1 + head * 16384;
    const float* B = g_WF + head * 16384;
    int tid = threadIdx.x, tx = tid & 15, ty = tid >> 4;
    u64 acc[4][4] = {};
    float4 ra = ldgA64(A, 128, mBase, kOff, tid);
    float4 rb0, rb1; ldgB(B, 128, kOff, tid, rb0, rb1);
    for (int s = 0; s < 4; s++) {
        __syncthreads();
        stsA64(sA, tid, ra); stsB(sB, tid, rb0, rb1);
        __syncthreads();
        if (s < 3) { ra = ldgA64(A, 128, mBase, kOff + (s + 1) * 16, tid); ldgB(B, 128, kOff + (s + 1) * 16, tid, rb0, rb1); }
        comp64(sA, sB, acc, tx, ty);
    }
    float* C = g_part1 + (size_t)(side * 4 + chunk) * 16384;
    int r0 = mBase + ty * 4;
#pragma unroll
    for (int u = 0; u < 4; u++) {
        *(float4*)(C + (r0 + u) * 128 + tx * 4)      = accrow(acc[u][0], acc[u][1]);
        *(float4*)(C + (r0 + u) * 128 + 64 + tx * 4) = accrow(acc[u][2], acc[u][3]);
    }
}

// ================= K4: G = sum 4 chunks + bb =================
__global__ __launch_bounds__(256) void k_redG()
{
    int side = blockIdx.y;
    int i4 = blockIdx.x * 256 + threadIdx.x;   // < 4096
    float4 s = ((const float4*)(g_bb + side * 128))[i4 & 31];
#pragma unroll
    for (int c = 0; c < 4; c++) {
        float4 p = ((const float4*)g_part1)[(size_t)(side * 4 + c) * 4096 + i4];
        s.x += p.x; s.y += p.y; s.z += p.z; s.w += p.w;
    }
    ((float4*)g_G)[side * 4096 + i4] = s;
}

// ================= K5: Htmp = relu(xt@G0 + xn@G1 + fb1) (BM=32) =================
__global__ __launch_bounds__(256) void k_Htmp(
    const float* __restrict__ xt, const float* __restrict__ xn,
    const float* __restrict__ fb1)
{
    __shared__ __align__(16) float sA[16 * 36];
    __shared__ __align__(16) float sB[16 * 128];
    int rowBase = blockIdx.x * 32;
    int tid = threadIdx.x, tx = tid & 15, ty = tid >> 4;
    u64 acc[2][4] = {};
#pragma unroll
    for (int pass = 0; pass < 2; pass++) {
        const float* A = pass ? xn : xt;
        const float* B = g_G + pass * 16384;
        float4 ra; if (tid < 128) ra = ldgA32(A, 128, rowBase, 0, tid);
        float4 rb0, rb1; ldgB(B, 128, 0, tid, rb0, rb1);
        for (int s = 0; s < 8; s++) {
            __syncthreads();
            if (tid < 128) stsA32(sA, tid, ra);
            stsB(sB, tid, rb0, rb1);
            __syncthreads();
            if (s < 7) { if (tid < 128) ra = ldgA32(A, 128, rowBase, (s + 1) * 16, tid); ldgB(B, 128, (s + 1) * 16, tid, rb0, rb1); }
            comp32(sA, sB, acc, tx, ty);
        }
        __syncthreads();
    }
    float4 bb0 = *(const float4*)(fb1 + tx * 4);
    float4 bb1 = *(const float4*)(fb1 + 64 + tx * 4);
    int r0 = rowBase + ty * 2;
#pragma unroll
    for (int u = 0; u < 2; u++) {
        float4 v0 = accrow(acc[u][0], acc[u][1]);
        float4 v1 = accrow(acc[u][2], acc[u][3]);
        v0.x = fmaxf(v0.x + bb0.x, 0.f); v0.y = fmaxf(v0.y + bb0.y, 0.f);
        v0.z = fmaxf(v0.z + bb0.z, 0.f); v0.w = fmaxf(v0.w + bb0.w, 0.f);
        v1.x = fmaxf(v1.x + bb1.x, 0.f); v1.y = fmaxf(v1.y + bb1.y, 0.f);
        v1.z = fmaxf(v1.z + bb1.z, 0.f); v1.w = fmaxf(v1.w + bb1.w, 0.f);
        *(float4*)(g_Htmp + (size_t)(r0 + u) * 128 + tx * 4) = v0;
        *(float4*)(g_Htmp + (size_t)(r0 + u) * 128 + 64 + tx * 4) = v1;
    }
}

// ================= K6: HrawT = (Htmp @ f_W2 + f_b2)^T  (BM=32, transposed store) =========
__global__ __launch_bounds__(256) void k_f2(
    const float* __restrict__ fW2, const float* __restrict__ fb2)
{
    __shared__ __align__(16) float sA[16 * 36];
    __shared__ __align__(16) float sB[16 * 128];
    __shared__ __align__(16) float sT[128 * 36];
    int rowBase = blockIdx.x * 32;
    int tid = threadIdx.x, tx = tid & 15, ty = tid >> 4;
    u64 acc[2][4] = {};
    float4 ra; if (tid < 128) ra = ldgA32(g_Htmp, 128, rowBase, 0, tid);
    float4 rb0, rb1; ldgB(fW2, 128, 0, tid, rb0, rb1);
    for (int s = 0; s < 8; s++) {
        __syncthreads();
        if (tid < 128) stsA32(sA, tid, ra);
        stsB(sB, tid, rb0, rb1);
        __syncthreads();
        if (s < 7) { if (tid < 128) ra = ldgA32(g_Htmp, 128, rowBase, (s + 1) * 16, tid); ldgB(fW2, 128, (s + 1) * 16, tid, rb0, rb1); }
        comp32(sA, sB, acc, tx, ty);
    }
    float4 bb0 = *(const float4*)(fb2 + tx * 4);
    float4 bb1 = *(const float4*)(fb2 + 64 + tx * 4);
#pragma unroll
    for (int u = 0; u < 2; u++) {
        int m = ty * 2 + u;
        float4 v0 = accrow(acc[u][0], acc[u][1]);
        float4 v1 = accrow(acc[u][2], acc[u][3]);
        v0.x += bb0.x; v0.y += bb0.y; v0.z += bb0.z; v0.w += bb0.w;
        v1.x += bb1.x; v1.y += bb1.y; v1.z += bb1.z; v1.w += bb1.w;
        int c0 = tx * 4;
        sT[(c0 + 0) * 36 + m] = v0.x; sT[(c0 + 1) * 36 + m] = v0.y;
        sT[(c0 + 2) * 36 + m] = v0.z; sT[(c0 + 3) * 36 + m] = v0.w;
        int c1 = 64 + tx * 4;
        sT[(c1 + 0) * 36 + m] = v1.x; sT[(c1 + 1) * 36 + m] = v1.y;
        sT[(c1 + 2) * 36 + m] = v1.z; sT[(c1 + 3) * 36 + m] = v1.w;
    }
    __syncthreads();
    // write HrawT: thread t -> column c = t>>1, half seg = t&1 (16 floats)
    int c = tid >> 1, seg = tid & 1;
#pragma unroll
    for (int j = 0; j < 4; j++) {
        float4 v = *(const float4*)(sT + c * 36 + seg * 16 + j * 4);
        *(float4*)(g_HrawT + (size_t)c * NTOT + rowBase + seg * 16 + j * 4) = v;
    }
}

// ================= K7: per-column standardize + softmax (fully coalesced on HT) ==========
__global__ __launch_bounds__(256) void k_colsm()
{
    int e = blockIdx.x;
    __shared__ float s[NTOT];
    int tid = threadIdx.x;
    const float* src = g_HrawT + (size_t)e * NTOT;
    for (int i = tid; i < NTOT / 4; i += 256)
        ((float4*)s)[i] = ((const float4*)src)[i];
    __syncthreads();

    float lsum = 0.f, lmaxx = -3.4e38f;
    for (int n = tid; n < NTOT; n += 256) { float x = s[n]; lsum += x; lmaxx = fmaxf(lmaxx, x); }
    float mean = block_sum<8>(lsum) * (1.f / NTOT);
    float maxx = block_max<8>(lmaxx);

    float lss = 0.f;
    for (int n = tid; n < NTOT; n += 256) { float d = s[n] - mean; lss += d * d; }
    float var = block_sum<8>(lss) * (1.f / (NTOT - 1));
    float inv = 1.f / (sqrtf(var) + EPSV);
    float mx = (maxx - mean) * inv;

    float lse = 0.f;
    for (int n = tid; n < NTOT; n += 256) {
        float z = (s[n] - mean) * inv;
        lse += __expf(z - mx);
    }
    float sum = block_sum<8>(lse);
    float invs = 1.f / sum;
    float lls = __logf(sum);

    float* ht = g_HT + (size_t)e * NTOT;
    float* lt = g_logHT + (size_t)e * NTOT;
    for (int n = tid; n < NTOT; n += 256) {
        float z = (s[n] - mean) * inv;
        ht[n] = __expf(z - mx) * invs;
        lt[n] = (z - mx) - lls;
    }
}

// ================= stageB: partZ(128 CTAs) + jsd(288 CTAs) in ONE launch =================
__global__ __launch_bounds__(256) void k_stageB()
{
    __shared__ __align__(16) float smem[3200];
    int tid = threadIdx.x;
    int bx = blockIdx.x;

    if (bx < 128) {
        // Z[e][d] = sum_n HT[e][n] * Y[n][d]; A = HT (NN layout, lda=2048)
        int side = bx >> 6;
        int r = bx & 63;
        int mBase = (r & 1) * 64;            // e-dim
        int kBeg = (r >> 1) * 64;            // n-dim
        float* sA = smem;
        float* sB = smem + 1088;
        const float* B = g_Y + (size_t)side * NTOT * 128;
        int tx = tid & 15, ty = tid >> 4;
        u64 acc[4][4] = {};
        float4 ra = ldgA64(g_HT, NTOT, mBase, kBeg, tid);
        float4 rb0, rb1; ldgB(B, 128, kBeg, tid, rb0, rb1);
        for (int s = 0; s < 4; s++) {
            __syncthreads();
            stsA64(sA, tid, ra); stsB(sB, tid, rb0, rb1);
            __syncthreads();
            if (s < 3) { ra = ldgA64(g_HT, NTOT, mBase, kBeg + (s + 1) * 16, tid); ldgB(B, 128, kBeg + (s + 1) * 16, tid, rb0, rb1); }
            comp64(sA, sB, acc, tx, ty);
        }
        float* C = g_partZ + (size_t)(side * 32 + (r >> 1)) * 16384;
        int r0 = mBase + ty * 4;
#pragma unroll
        for (int u = 0; u < 4; u++) {
            *(float4*)(C + (r0 + u) * 128 + tx * 4)      = accrow(acc[u][0], acc[u][1]);
            *(float4*)(C + (r0 + u) * 128 + 64 + tx * 4) = accrow(acc[u][2], acc[u][3]);
        }
    } else {
        int idx = bx - 128;
        int t = idx % 36;
        int nch = idx / 36;
        int bi = 0, rem = t;
        while (rem >= 8 - bi) { rem -= 8 - bi; bi++; }
        int bj = bi + rem;
        int ti = tid & 15, tj = tid >> 4;
        int i = bi * 16 + ti, j = bj * 16 + tj;

        float* sHi = smem;            // [16 n][17] stride 17
        float* sLi = smem + 272;
        float* sHj = smem + 544;
        float* sLj = smem + 816;
        float* red = smem + 1088;     // [16][16]

        float acci = 0.f, accj = 0.f;
        int a = tid & 15, b = tid >> 4;  // a = n-local (coalesced), b = e-local
        int nBeg = nch * 256;

        for (int n0 = nBeg; n0 < nBeg + 256; n0 += 16) {
            __syncthreads();
            size_t oi = (size_t)(bi * 16 + b) * NTOT + n0 + a;
            size_t oj = (size_t)(bj * 16 + b) * NTOT + n0 + a;
            sHi[a * 17 + b] = g_HT[oi];
            sLi[a * 17 + b] = g_logHT[oi];
            sHj[a * 17 + b] = g_HT[oj];
            sLj[a * 17 + b] = g_logHT[oj];
            __syncthreads();
#pragma unroll
            for (int r2 = 0; r2 < 16; r2++) {
                float hi = sHi[r2 * 17 + ti], hj = sHj[r2 * 17 + tj];
                float m  = 0.5f * (hi + hj);
                float lm = __logf(m);
                acci += hi * (sLi[r2 * 17 + ti] - lm);
                accj += hj * (sLj[r2 * 17 + tj] - lm);
            }
        }
        float v = (i < j) ? 0.5f * (acci + accj) : 0.f;

        __syncthreads();
        red[tj * 16 + ti] = v;
        __syncthreads();

        float* out = g_jpart + (size_t)(nch * 36 + t) * 128;
        if (tid < 128) out[tid] = 0.f;
        __syncthreads();
        if (tid < 16) {
            float si = 0.f, sj = 0.f;
#pragma unroll
            for (int r2 = 0; r2 < 16; r2++) { si += red[r2 * 16 + tid]; sj += red[tid * 16 + r2]; }
            out[bi * 16 + tid] += si;
            out[bj * 16 + tid] += sj;
        }
    }
}

// ================= K9: jm -> standardized -> softmax -> w =================
__global__ __launch_bounds__(128) void k_w()
{
    int e = threadIdx.x;
    float cs = 0.f;
    for (int r = 0; r < JROWS; r++) cs += g_jpart[r * 128 + e];
    float jm = cs * (1.f / 128.f);

    float mean = block_sum<4>(jm) * (1.f / 128.f);
    float d = jm - mean;
    float var = block_sum<4>(d * d) * (1.f / 127.f);
    float njm = d / (sqrtf(var) + EPSV);

    float mx = block_max<4>(njm);
    float ex = __expf(njm - mx);
    float sum = block_sum<4>(ex);
    g_w[e] = ex / sum;
}

// ================= K12: Zw = w * (sum chunks) =================
__global__ __launch_bounds__(256) void k_redZ()
{
    int side = blockIdx.y;
    int i4 = blockIdx.x * 256 + threadIdx.x;   // < 4096
    float4 s = make_float4(0.f, 0.f, 0.f, 0.f);
#pragma unroll
    for (int c = 0; c < 32; c++) {
        float4 p = ((const float4*)g_partZ)[(size_t)(side * 32 + c) * 4096 + i4];
        s.x += p.x; s.y += p.y; s.z += p.z; s.w += p.w;
    }
    float wv = g_w[i4 >> 5];
    s.x *= wv; s.y *= wv; s.z *= wv; s.w *= wv;
    ((float4*)g_Zw)[side * 4096 + i4] = s;
}

// ================= K13: out = x + elu(H @ Zw)  (A from HT, BM=32) =================
__global__ __launch_bounds__(256) void k_final(
    const float* __restrict__ xt, const float* __restrict__ xn,
    float* __restrict__ out)
{
    __shared__ __align__(16) float sA[16 * 36];
    __shared__ __align__(16) float sB[16 * 128];
    int side = blockIdx.z;
    const float* x = side ? xn : xt;
    const float* B = g_Zw + side * 16384;
    int rowBase = blockIdx.x * 32;               // n-dim
    int tid = threadIdx.x, tx = tid & 15, ty = tid >> 4;
    u64 acc[2][4] = {};
    float4 rb0, rb1; ldgB(B, 128, 0, tid, rb0, rb1);
    for (int s = 0; s < 8; s++) {
        __syncthreads();
        if (tid < 128) ldstA_HT(g_HT, sA, rowBase, s * 16, tid);
        stsB(sB, tid, rb0, rb1);
        __syncthreads();
        if (s < 7) ldgB(B, 128, (s + 1) * 16, tid, rb0, rb1);
        comp32(sA, sB, acc, tx, ty);
    }
    float* o = out + (size_t)side * NTOT * 128;
    int r0 = rowBase + ty * 2;
#pragma unroll
    for (int u = 0; u < 2; u++) {
#pragma unroll
        for (int h = 0; h < 2; h++) {
            float4 v = accrow(acc[u][h * 2], acc[u][h * 2 + 1]);
            int c = h * 64 + tx * 4;
            float4 xv = *(const float4*)(x + (size_t)(r0 + u) * 128 + c);
            v.x = xv.x + ((v.x > 0.f) ? v.x : expm1f(v.x));
            v.y = xv.y + ((v.y > 0.f) ? v.y : expm1f(v.y));
            v.z = xv.z + ((v.z > 0.f) ? v.z : expm1f(v.z));
            v.w = xv.w + ((v.w > 0.f) ? v.w : expm1f(v.w));
            *(float4*)(o + (size_t)(r0 + u) * 128 + c) = v;
        }
    }
}

// ---------------- launch ----------------
extern "C" void kernel_launch(void* const* d_in, const int* in_sizes, int n_in,
                              void* d_out, int out_size)
{
    const float* xt    = (const float*)d_in[0];
    const float* xn    = (const float*)d_in[1];
    const float* itW1  = (const float*)d_in[2];
    const float* itb1  = (const float*)d_in[3];
    const float* itW2  = (const float*)d_in[4];
    const float* itb2  = (const float*)d_in[5];
    const float* inwW1 = (const float*)d_in[6];
    const float* inwb1 = (const float*)d_in[7];
    const float* inwW2 = (const float*)d_in[8];
    const float* inwb2 = (const float*)d_in[9];
    const float* t2nW1 = (const float*)d_in[10];
    const float* t2nb1 = (const float*)d_in[11];
    const float* t2nW2 = (const float*)d_in[12];
    const float* t2nb2 = (const float*)d_in[13];
    const float* n2tW1 = (const float*)d_in[14];
    const float* n2tb1 = (const float*)d_in[15];
    const float* n2tW2 = (const float*)d_in[16];
    const float* n2tb2 = (const float*)d_in[17];
    const float* fW1   = (const float*)d_in[18];
    const float* fb1   = (const float*)d_in[19];
    const float* fW2   = (const float*)d_in[20];
    const float* fb2   = (const float*)d_in[21];
    const float* thT   = (const float*)d_in[22];
    const float* thN   = (const float*)d_in[23];
    float* out = (float*)d_out;

    k_stageA<<<209, 256>>>(xt, xn, itW1, inwW1, t2nW1, n2tW1, thT, thN,
                           itW2, inwW2, t2nW2, n2tW2, fW1,
                           itb2, inwb2, t2nb2, n2tb2);
    k_red1 <<<dim3(16, 4), 256>>>(itb1, inwb1, t2nb1, n2tb1);
    k_G    <<<dim3(2, 4, 2), 256>>>();
    k_redG <<<dim3(16, 2), 256>>>();
    k_Htmp <<<64, 256>>>(xt, xn, fb1);
    k_f2   <<<64, 256>>>(fW2, fb2);
    k_colsm<<<128, 256>>>();
    k_stageB<<<416, 256>>>();
    k_w    <<<1, 128>>>();
    k_redZ <<<dim3(16, 2), 256>>>();
    k_final<<<dim3(64, 1, 2), 256>>>(xt, xn, out);
}